// round 1
// baseline (speedup 1.0000x reference)
#include <cuda_runtime.h>

#define D 128
#define VCAP 100000
#define CAP 128          // adjacency slots per node (max degree << 128)
#define GB_ROWS 64       // GEMM rows per tile
#define WS 260           // wsT row stride in floats (256 cols + pad, /4 aligned)

// ---------------- scratch (static device globals; no allocs) ----------------
__device__ float g_h0[(size_t)VCAP * D];
__device__ float g_h1[(size_t)VCAP * D];
__device__ float g_y [(size_t)VCAP * D];
__device__ float g_xA[(size_t)VCAP * D];
__device__ float g_xB[(size_t)VCAP * D];
__device__ int   g_adj[(size_t)VCAP * CAP];
__device__ int   g_cnt[VCAP];
__device__ float g_dinv[VCAP];
__device__ float g_stats[3 * 2 * D];   // per layer: [0..127]=colsum, [128..255]=colsumsq

// ---------------- prologue kernels ----------------
__global__ void zero_kernel(int V) {
    int i = blockIdx.x * blockDim.x + threadIdx.x;
    if (i < V) g_cnt[i] = 0;
    if (i < 3 * 2 * D) g_stats[i] = 0.0f;
}

__global__ void build_adj(const int* __restrict__ edges, int E) {
    int e = blockIdx.x * blockDim.x + threadIdx.x;
    if (e >= E) return;
    int a = edges[2 * e];
    int b = edges[2 * e + 1];
    int pa = atomicAdd(&g_cnt[a], 1);
    if (pa < CAP) g_adj[(size_t)a * CAP + pa] = b;
    int pb = atomicAdd(&g_cnt[b], 1);
    if (pb < CAP) g_adj[(size_t)b * CAP + pb] = a;
}

__global__ void dinv_kernel(int V) {
    int i = blockIdx.x * blockDim.x + threadIdx.x;
    if (i < V) g_dinv[i] = 1.0f / (1.0f + (float)g_cnt[i]);
}

// ---------------- dual GEMM: h0 = x @ W0^T + b0 ; h1 = x @ W1^T + b1 ----------------
// Persistent blocks; entire transposed W0||W1 (256 x 128) resident in SMEM.
__global__ void __launch_bounds__(256, 1) gemm_dual(
    const float* __restrict__ xext,  int xsel,
    const float* __restrict__ W0, const float* __restrict__ b0,
    const float* __restrict__ W1, const float* __restrict__ b1,
    int V)
{
    extern __shared__ float smem[];
    float* wsT = smem;                 // [128][WS]   wsT[k*WS + col], col 0..255
    float* xs  = smem + 128 * WS;      // [64][128]

    const float* x = (xsel == 0) ? xext : (xsel == 1 ? g_xA : g_xB);

    int tid = threadIdx.x;

    // --- load W0,W1 transposed into SMEM once per block ---
    {
        int kk4 = (tid & 7) * 4;     // float4 k-offset within 32-chunk
        int c0  = tid >> 3;          // 0..31
        for (int cb = 0; cb < 8; cb++) {
            int col = c0 + cb * 32;  // 0..255
            const float* Wp = (col < D) ? (W0 + (size_t)col * D)
                                        : (W1 + (size_t)(col - D) * D);
            #pragma unroll
            for (int kb = 0; kb < 4; kb++) {
                int kk = kb * 32 + kk4;
                float4 g = *(const float4*)(Wp + kk);
                wsT[(kk + 0) * WS + col] = g.x;
                wsT[(kk + 1) * WS + col] = g.y;
                wsT[(kk + 2) * WS + col] = g.z;
                wsT[(kk + 3) * WS + col] = g.w;
            }
        }
    }
    __syncthreads();

    int ry = tid >> 5;   // 0..7  -> rows ry*8 .. ry*8+7
    int cx = tid & 31;   // 0..31 -> cols cx*4..cx*4+3 (both h0 and h1 halves)

    float4 bq0 = *(const float4*)(b0 + cx * 4);
    float4 bq1 = *(const float4*)(b1 + cx * 4);

    int numTiles = (V + GB_ROWS - 1) / GB_ROWS;
    for (int t = blockIdx.x; t < numTiles; t += gridDim.x) {
        int r0 = t * GB_ROWS;

        // load x tile (64 x 128) -> 2048 float4, 8 per thread, coalesced
        #pragma unroll
        for (int it = 0; it < 8; it++) {
            int f   = tid + it * 256;
            int r   = f >> 5;
            int c4  = (f & 31) * 4;
            int row = r0 + r;
            float4 g = (row < V) ? *(const float4*)(x + (size_t)row * D + c4)
                                 : make_float4(0.f, 0.f, 0.f, 0.f);
            *(float4*)(xs + r * D + c4) = g;
        }
        __syncthreads();

        float acc0[8][4];
        float acc1[8][4];
        #pragma unroll
        for (int i = 0; i < 8; i++)
            #pragma unroll
            for (int j = 0; j < 4; j++) { acc0[i][j] = 0.f; acc1[i][j] = 0.f; }

        #pragma unroll 4
        for (int k = 0; k < D; k++) {
            float4 bv0 = *(const float4*)(wsT + k * WS + cx * 4);
            float4 bv1 = *(const float4*)(wsT + k * WS + 128 + cx * 4);
            #pragma unroll
            for (int i = 0; i < 8; i++) {
                float a = xs[(ry * 8 + i) * D + k];   // warp-broadcast
                acc0[i][0] = fmaf(a, bv0.x, acc0[i][0]);
                acc0[i][1] = fmaf(a, bv0.y, acc0[i][1]);
                acc0[i][2] = fmaf(a, bv0.z, acc0[i][2]);
                acc0[i][3] = fmaf(a, bv0.w, acc0[i][3]);
                acc1[i][0] = fmaf(a, bv1.x, acc1[i][0]);
                acc1[i][1] = fmaf(a, bv1.y, acc1[i][1]);
                acc1[i][2] = fmaf(a, bv1.z, acc1[i][2]);
                acc1[i][3] = fmaf(a, bv1.w, acc1[i][3]);
            }
        }

        #pragma unroll
        for (int i = 0; i < 8; i++) {
            int row = r0 + ry * 8 + i;
            if (row < V) {
                float4 o0 = make_float4(acc0[i][0] + bq0.x, acc0[i][1] + bq0.y,
                                        acc0[i][2] + bq0.z, acc0[i][3] + bq0.w);
                float4 o1 = make_float4(acc1[i][0] + bq1.x, acc1[i][1] + bq1.y,
                                        acc1[i][2] + bq1.z, acc1[i][3] + bq1.w);
                *(float4*)(g_h0 + (size_t)row * D + cx * 4) = o0;
                *(float4*)(g_h1 + (size_t)row * D + cx * 4) = o1;
            }
        }
        __syncthreads();   // protect xs before next tile load
    }
}

// ---------------- aggregation: y[v] = dinv[v]*(h0[v] + sum_{u in N(v)} h1[u]) ----------------
// warp per node (gather, no feature atomics); folds BN column sum/sumsq stats.
__global__ void __launch_bounds__(256) agg_kernel(float* __restrict__ stats, int V)
{
    __shared__ float s_sum[D];
    __shared__ float s_sq[D];

    int tid  = threadIdx.x;
    int wid  = tid >> 5;
    int lane = tid & 31;
    int c0   = lane * 4;

    if (tid < D) { s_sum[tid] = 0.f; s_sq[tid] = 0.f; }
    __syncthreads();

    float4 psum = make_float4(0.f, 0.f, 0.f, 0.f);
    float4 psq  = make_float4(0.f, 0.f, 0.f, 0.f);

    int warpStride = gridDim.x * 8;
    for (int v = blockIdx.x * 8 + wid; v < V; v += warpStride) {
        float4 acc = *(const float4*)(g_h0 + (size_t)v * D + c0);
        int n = g_cnt[v];
        const int* ap = g_adj + (size_t)v * CAP;
        int e = 0;
        for (; e + 1 < n; e += 2) {
            int u0 = ap[e];
            int u1 = ap[e + 1];
            float4 t0 = *(const float4*)(g_h1 + (size_t)u0 * D + c0);
            float4 t1 = *(const float4*)(g_h1 + (size_t)u1 * D + c0);
            acc.x += t0.x + t1.x;
            acc.y += t0.y + t1.y;
            acc.z += t0.z + t1.z;
            acc.w += t0.w + t1.w;
        }
        if (e < n) {
            int u = ap[e];
            float4 t = *(const float4*)(g_h1 + (size_t)u * D + c0);
            acc.x += t.x; acc.y += t.y; acc.z += t.z; acc.w += t.w;
        }
        float dv = g_dinv[v];
        acc.x *= dv; acc.y *= dv; acc.z *= dv; acc.w *= dv;
        *(float4*)(g_y + (size_t)v * D + c0) = acc;

        psum.x += acc.x; psum.y += acc.y; psum.z += acc.z; psum.w += acc.w;
        psq.x  += acc.x * acc.x; psq.y += acc.y * acc.y;
        psq.z  += acc.z * acc.z; psq.w += acc.w * acc.w;
    }

    atomicAdd(&s_sum[c0 + 0], psum.x);
    atomicAdd(&s_sum[c0 + 1], psum.y);
    atomicAdd(&s_sum[c0 + 2], psum.z);
    atomicAdd(&s_sum[c0 + 3], psum.w);
    atomicAdd(&s_sq[c0 + 0],  psq.x);
    atomicAdd(&s_sq[c0 + 1],  psq.y);
    atomicAdd(&s_sq[c0 + 2],  psq.z);
    atomicAdd(&s_sq[c0 + 3],  psq.w);
    __syncthreads();

    if (tid < D) {
        atomicAdd(&stats[tid],     s_sum[tid]);
        atomicAdd(&stats[D + tid], s_sq[tid]);
    }
}

// ---------------- BN normalize + ReLU (+ residual) ----------------
__global__ void __launch_bounds__(256) norm_kernel(
    const float* __restrict__ stats,
    const float* __restrict__ gamma, const float* __restrict__ beta,
    const float* __restrict__ res,   // nullptr except layer 2
    float* __restrict__ outext, int osel,   // 0 -> g_xA, 1 -> g_xB, 2 -> outext
    int V, float invV)
{
    __shared__ float s_scale[D];
    __shared__ float s_shift[D];

    float* out = (osel == 0) ? g_xA : (osel == 1 ? g_xB : outext);

    int tid = threadIdx.x;
    if (tid < D) {
        float mu  = stats[tid] * invV;
        float var = stats[D + tid] * invV - mu * mu;
        float rs  = rsqrtf(var + 1e-5f);
        float sc  = gamma[tid] * rs;
        s_scale[tid] = sc;
        s_shift[tid] = beta[tid] - mu * sc;
    }
    __syncthreads();

    int total = V * (D / 4);  // float4 count
    for (int f = blockIdx.x * blockDim.x + tid; f < total; f += gridDim.x * blockDim.x) {
        int c = (f & 31) * 4;
        float4 t = *(const float4*)(g_y + (size_t)f * 4);
        float4 o;
        o.x = t.x * s_scale[c + 0] + s_shift[c + 0];
        o.y = t.y * s_scale[c + 1] + s_shift[c + 1];
        o.z = t.z * s_scale[c + 2] + s_shift[c + 2];
        o.w = t.w * s_scale[c + 3] + s_shift[c + 3];
        if (res) {
            float4 r = *(const float4*)(res + (size_t)f * 4);
            o.x += r.x; o.y += r.y; o.z += r.z; o.w += r.w;
        }
        o.x = fmaxf(o.x, 0.f);
        o.y = fmaxf(o.y, 0.f);
        o.z = fmaxf(o.z, 0.f);
        o.w = fmaxf(o.w, 0.f);
        *(float4*)(out + (size_t)f * 4) = o;
    }
}

// ---------------- launch ----------------
extern "C" void kernel_launch(void* const* d_in, const int* in_sizes, int n_in,
                              void* d_out, int out_size)
{
    const float* features = (const float*)d_in[0];
    const int*   edges    = (const int*)  d_in[1];
    const float* W0       = (const float*)d_in[2];
    const float* b0       = (const float*)d_in[3];
    const float* W1       = (const float*)d_in[4];
    const float* b1       = (const float*)d_in[5];
    const float* gamma    = (const float*)d_in[6];
    const float* beta     = (const float*)d_in[7];
    float* out = (float*)d_out;

    int V = in_sizes[0] / D;
    int E = in_sizes[1] / 2;

    const int SMEM_BYTES = (128 * WS + GB_ROWS * D) * (int)sizeof(float);
    cudaFuncSetAttribute(gemm_dual, cudaFuncAttributeMaxDynamicSharedMemorySize, SMEM_BYTES);

    float* statsP = nullptr;
    cudaGetSymbolAddress((void**)&statsP, g_stats);

    zero_kernel<<<(V + 255) / 256, 256>>>(V);
    build_adj<<<(E + 255) / 256, 256>>>(edges, E);
    dinv_kernel<<<(V + 255) / 256, 256>>>(V);

    for (int l = 0; l < 3; l++) {
        gemm_dual<<<148, 256, SMEM_BYTES>>>(
            features, l,                     // xsel: 0=features, 1=g_xA, 2=g_xB
            W0 + (size_t)l * D * D, b0 + (size_t)l * D,
            W1 + (size_t)l * D * D, b1 + (size_t)l * D, V);

        agg_kernel<<<592, 256>>>(statsP + l * 2 * D, V);

        const float* res = (l == 2) ? features : nullptr;
        norm_kernel<<<592, 256>>>(statsP + l * 2 * D,
                                  gamma + (size_t)l * D, beta + (size_t)l * D,
                                  res, out, l,            // osel: 0->xA, 1->xB, 2->out
                                  V, 1.0f / (float)V);
    }
}

// round 2
// speedup vs baseline: 1.0270x; 1.0270x over previous
#include <cuda_runtime.h>

#define D 128
#define VCAP 100000
#define CAP 128          // adjacency slots per node
#define GB_ROWS 96       // GEMM rows per tile
#define NTHR 384         // 12 warps
#define WS 260           // wsT row stride in floats (256 cols + pad)

// packed f32x2 FMA: acc = a*b + acc (lanewise on 2 packed fp32)
#define FMA2(acc, a, b) \
    asm("fma.rn.f32x2 %0, %1, %2, %0;" : "+l"(acc) : "l"(a), "l"(b))

__device__ __forceinline__ unsigned long long splat2(float v) {
    unsigned long long r;
    unsigned int u = __float_as_uint(v);
    asm("mov.b64 %0, {%1, %1};" : "=l"(r) : "r"(u));
    return r;
}
__device__ __forceinline__ unsigned long long pack2(float lo, float hi) {
    unsigned long long r;
    asm("mov.b64 %0, {%1, %2};" : "=l"(r) : "r"(__float_as_uint(lo)), "r"(__float_as_uint(hi)));
    return r;
}
__device__ __forceinline__ void unpack2(unsigned long long p, float& lo, float& hi) {
    asm("mov.b64 {%0, %1}, %2;" : "=f"(lo), "=f"(hi) : "l"(p));
}

// ---------------- scratch (static device globals; no allocs) ----------------
__device__ float g_h0[(size_t)VCAP * D];
__device__ float g_h1[(size_t)VCAP * D];
__device__ float g_y [(size_t)VCAP * D];
__device__ int   g_adj[(size_t)VCAP * CAP];
__device__ int   g_cnt[VCAP];
__device__ float g_dinv[VCAP];
__device__ float g_stats[3 * 2 * D];   // per layer: [0..127]=colsum, [128..255]=colsumsq

// ---------------- prologue kernels ----------------
__global__ void zero_kernel(int V) {
    int i = blockIdx.x * blockDim.x + threadIdx.x;
    if (i < V) g_cnt[i] = 0;
    if (i < 3 * 2 * D) g_stats[i] = 0.0f;
}

__global__ void build_adj(const int* __restrict__ edges, int E) {
    int e = blockIdx.x * blockDim.x + threadIdx.x;
    if (e >= E) return;
    int a = edges[2 * e];
    int b = edges[2 * e + 1];
    int pa = atomicAdd(&g_cnt[a], 1);
    if (pa < CAP) g_adj[(size_t)a * CAP + pa] = b;
    int pb = atomicAdd(&g_cnt[b], 1);
    if (pb < CAP) g_adj[(size_t)b * CAP + pb] = a;
}

__global__ void dinv_kernel(int V) {
    int i = blockIdx.x * blockDim.x + threadIdx.x;
    if (i < V) g_dinv[i] = 1.0f / (1.0f + (float)g_cnt[i]);
}

// ---------------- dual GEMM (FFMA2) with fused BN+ReLU on input ----------------
// h0 = f(x) @ W0^T + b0 ; h1 = f(x) @ W1^T + b1
// f(x) = x for layer 0, else relu(x*scale + shift) per column (BN of prev layer).
__global__ void __launch_bounds__(NTHR, 1) gemm_dual(
    const float* __restrict__ xext, int layer,
    const float* __restrict__ W0, const float* __restrict__ b0,
    const float* __restrict__ W1, const float* __restrict__ b1,
    const float* __restrict__ gammaPrev, const float* __restrict__ betaPrev,
    int V, float invV)
{
    extern __shared__ float smem[];
    float* wsT = smem;                 // [128][WS]  wsT[k*WS + col], col 0..255
    float* xs  = smem + 128 * WS;      // [GB_ROWS][128]
    __shared__ float s_sc[D];
    __shared__ float s_sh[D];

    const float* x = (layer == 0) ? xext : g_y;
    const bool doNorm = (layer != 0);

    int tid = threadIdx.x;

    // per-column BN scale/shift of previous layer
    if (doNorm && tid < D) {
        const float* st = g_stats + (layer - 1) * 2 * D;
        float mu  = st[tid] * invV;
        float var = st[D + tid] * invV - mu * mu;
        float rs  = rsqrtf(var + 1e-5f);
        float sc  = gammaPrev[tid] * rs;
        s_sc[tid] = sc;
        s_sh[tid] = betaPrev[tid] - mu * sc;
    }

    // --- load W0,W1 transposed into SMEM once per block ---
    {
        int kk4 = (tid & 7) * 4;
        int c0  = tid >> 3;          // 0..47
        for (int col = c0; col < 256; col += 48) {
            const float* Wp = (col < D) ? (W0 + (size_t)col * D)
                                        : (W1 + (size_t)(col - D) * D);
            #pragma unroll
            for (int kb = 0; kb < 4; kb++) {
                int kk = kb * 32 + kk4;
                float4 g = *(const float4*)(Wp + kk);
                wsT[(kk + 0) * WS + col] = g.x;
                wsT[(kk + 1) * WS + col] = g.y;
                wsT[(kk + 2) * WS + col] = g.z;
                wsT[(kk + 3) * WS + col] = g.w;
            }
        }
    }
    __syncthreads();

    int wid  = tid >> 5;     // 0..11 -> rows wid*8 .. wid*8+7
    int lane = tid & 31;
    int ry8  = wid * 8;
    int cx4  = lane * 4;

    float4 bq0 = *(const float4*)(b0 + cx4);
    float4 bq1 = *(const float4*)(b1 + cx4);
    unsigned long long bias0[2] = { pack2(bq0.x, bq0.y), pack2(bq0.z, bq0.w) };
    unsigned long long bias1[2] = { pack2(bq1.x, bq1.y), pack2(bq1.z, bq1.w) };

    int numTiles = (V + GB_ROWS - 1) / GB_ROWS;
    for (int t = blockIdx.x; t < numTiles; t += gridDim.x) {
        int r0 = t * GB_ROWS;

        // load x tile (96 x 128) -> 3072 float4, 8 per thread, coalesced;
        // apply BN scale/shift + ReLU on the fly for layers 1,2.
        #pragma unroll
        for (int it = 0; it < 8; it++) {
            int f   = tid + it * NTHR;
            int r   = f >> 5;
            int c4  = (f & 31) * 4;
            int row = r0 + r;
            float4 g = (row < V) ? *(const float4*)(x + (size_t)row * D + c4)
                                 : make_float4(0.f, 0.f, 0.f, 0.f);
            if (doNorm && row < V) {
                g.x = fmaxf(fmaf(g.x, s_sc[c4 + 0], s_sh[c4 + 0]), 0.f);
                g.y = fmaxf(fmaf(g.y, s_sc[c4 + 1], s_sh[c4 + 1]), 0.f);
                g.z = fmaxf(fmaf(g.z, s_sc[c4 + 2], s_sh[c4 + 2]), 0.f);
                g.w = fmaxf(fmaf(g.w, s_sc[c4 + 3], s_sh[c4 + 3]), 0.f);
            }
            *(float4*)(xs + r * D + c4) = g;
        }
        __syncthreads();

        unsigned long long acc0[8][2];
        unsigned long long acc1[8][2];
        #pragma unroll
        for (int i = 0; i < 8; i++) {
            acc0[i][0] = bias0[0]; acc0[i][1] = bias0[1];
            acc1[i][0] = bias1[0]; acc1[i][1] = bias1[1];
        }

        for (int kq = 0; kq < D / 4; kq++) {
            float4 a4[8];
            #pragma unroll
            for (int i = 0; i < 8; i++)
                a4[i] = *(const float4*)(xs + (ry8 + i) * D + kq * 4);

            #pragma unroll
            for (int kk = 0; kk < 4; kk++) {
                const float* wrow = wsT + (kq * 4 + kk) * WS + cx4;
                ulonglong2 bv0 = *(const ulonglong2*)(wrow);
                ulonglong2 bv1 = *(const ulonglong2*)(wrow + 128);
                #pragma unroll
                for (int i = 0; i < 8; i++) {
                    float av = (kk == 0) ? a4[i].x : (kk == 1) ? a4[i].y
                             : (kk == 2) ? a4[i].z : a4[i].w;
                    unsigned long long ap = splat2(av);
                    FMA2(acc0[i][0], ap, bv0.x);
                    FMA2(acc0[i][1], ap, bv0.y);
                    FMA2(acc1[i][0], ap, bv1.x);
                    FMA2(acc1[i][1], ap, bv1.y);
                }
            }
        }

        #pragma unroll
        for (int i = 0; i < 8; i++) {
            int row = r0 + ry8 + i;
            if (row < V) {
                float4 o0, o1;
                unpack2(acc0[i][0], o0.x, o0.y);
                unpack2(acc0[i][1], o0.z, o0.w);
                unpack2(acc1[i][0], o1.x, o1.y);
                unpack2(acc1[i][1], o1.z, o1.w);
                *(float4*)(g_h0 + (size_t)row * D + cx4) = o0;
                *(float4*)(g_h1 + (size_t)row * D + cx4) = o1;
            }
        }
        __syncthreads();
    }
}

// ---------------- aggregation + BN stats ----------------
__global__ void __launch_bounds__(256) agg_kernel(float* __restrict__ stats, int V)
{
    __shared__ float s_sum[D];
    __shared__ float s_sq[D];

    int tid  = threadIdx.x;
    int wid  = tid >> 5;
    int lane = tid & 31;
    int c0   = lane * 4;

    if (tid < D) { s_sum[tid] = 0.f; s_sq[tid] = 0.f; }
    __syncthreads();

    float4 psum = make_float4(0.f, 0.f, 0.f, 0.f);
    float4 psq  = make_float4(0.f, 0.f, 0.f, 0.f);

    int warpStride = gridDim.x * 8;
    for (int v = blockIdx.x * 8 + wid; v < V; v += warpStride) {
        float4 acc = *(const float4*)(g_h0 + (size_t)v * D + c0);
        int n = g_cnt[v];
        const int* ap = g_adj + (size_t)v * CAP;
        int e = 0;
        for (; e + 1 < n; e += 2) {
            int u0 = ap[e];
            int u1 = ap[e + 1];
            float4 t0 = *(const float4*)(g_h1 + (size_t)u0 * D + c0);
            float4 t1 = *(const float4*)(g_h1 + (size_t)u1 * D + c0);
            acc.x += t0.x + t1.x;
            acc.y += t0.y + t1.y;
            acc.z += t0.z + t1.z;
            acc.w += t0.w + t1.w;
        }
        if (e < n) {
            int u = ap[e];
            float4 t = *(const float4*)(g_h1 + (size_t)u * D + c0);
            acc.x += t.x; acc.y += t.y; acc.z += t.z; acc.w += t.w;
        }
        float dv = g_dinv[v];
        acc.x *= dv; acc.y *= dv; acc.z *= dv; acc.w *= dv;
        *(float4*)(g_y + (size_t)v * D + c0) = acc;

        psum.x += acc.x; psum.y += acc.y; psum.z += acc.z; psum.w += acc.w;
        psq.x  += acc.x * acc.x; psq.y += acc.y * acc.y;
        psq.z  += acc.z * acc.z; psq.w += acc.w * acc.w;
    }

    atomicAdd(&s_sum[c0 + 0], psum.x);
    atomicAdd(&s_sum[c0 + 1], psum.y);
    atomicAdd(&s_sum[c0 + 2], psum.z);
    atomicAdd(&s_sum[c0 + 3], psum.w);
    atomicAdd(&s_sq[c0 + 0],  psq.x);
    atomicAdd(&s_sq[c0 + 1],  psq.y);
    atomicAdd(&s_sq[c0 + 2],  psq.z);
    atomicAdd(&s_sq[c0 + 3],  psq.w);
    __syncthreads();

    if (tid < D) {
        atomicAdd(&stats[tid],     s_sum[tid]);
        atomicAdd(&stats[D + tid], s_sq[tid]);
    }
}

// ---------------- final BN + ReLU + residual -> out ----------------
__global__ void __launch_bounds__(256) norm_final(
    const float* __restrict__ stats,
    const float* __restrict__ gamma, const float* __restrict__ beta,
    const float* __restrict__ res,
    float* __restrict__ out, int V, float invV)
{
    __shared__ float s_scale[D];
    __shared__ float s_shift[D];

    int tid = threadIdx.x;
    if (tid < D) {
        float mu  = stats[tid] * invV;
        float var = stats[D + tid] * invV - mu * mu;
        float rs  = rsqrtf(var + 1e-5f);
        float sc  = gamma[tid] * rs;
        s_scale[tid] = sc;
        s_shift[tid] = beta[tid] - mu * sc;
    }
    __syncthreads();

    int total = V * (D / 4);
    for (int f = blockIdx.x * blockDim.x + tid; f < total; f += gridDim.x * blockDim.x) {
        int c = (f & 31) * 4;
        float4 t = *(const float4*)(g_y + (size_t)f * 4);
        float4 r = *(const float4*)(res + (size_t)f * 4);
        float4 o;
        o.x = fmaxf(fmaf(t.x, s_scale[c + 0], s_shift[c + 0]) + r.x, 0.f);
        o.y = fmaxf(fmaf(t.y, s_scale[c + 1], s_shift[c + 1]) + r.y, 0.f);
        o.z = fmaxf(fmaf(t.z, s_scale[c + 2], s_shift[c + 2]) + r.z, 0.f);
        o.w = fmaxf(fmaf(t.w, s_scale[c + 3], s_shift[c + 3]) + r.w, 0.f);
        *(float4*)(out + (size_t)f * 4) = o;
    }
}

// ---------------- launch ----------------
extern "C" void kernel_launch(void* const* d_in, const int* in_sizes, int n_in,
                              void* d_out, int out_size)
{
    const float* features = (const float*)d_in[0];
    const int*   edges    = (const int*)  d_in[1];
    const float* W0       = (const float*)d_in[2];
    const float* b0       = (const float*)d_in[3];
    const float* W1       = (const float*)d_in[4];
    const float* b1       = (const float*)d_in[5];
    const float* gamma    = (const float*)d_in[6];
    const float* beta     = (const float*)d_in[7];
    float* out = (float*)d_out;

    int V = in_sizes[0] / D;
    int E = in_sizes[1] / 2;
    float invV = 1.0f / (float)V;

    const int SMEM_BYTES = (128 * WS + GB_ROWS * D) * (int)sizeof(float);
    cudaFuncSetAttribute(gemm_dual, cudaFuncAttributeMaxDynamicSharedMemorySize, SMEM_BYTES);

    float* statsP = nullptr;
    cudaGetSymbolAddress((void**)&statsP, g_stats);

    zero_kernel<<<(V + 255) / 256, 256>>>(V);
    build_adj<<<(E + 255) / 256, 256>>>(edges, E);
    dinv_kernel<<<(V + 255) / 256, 256>>>(V);

    for (int l = 0; l < 3; l++) {
        const float* gPrev = (l == 0) ? nullptr : gamma + (size_t)(l - 1) * D;
        const float* bPrev = (l == 0) ? nullptr : beta  + (size_t)(l - 1) * D;
        gemm_dual<<<148, NTHR, SMEM_BYTES>>>(
            features, l,
            W0 + (size_t)l * D * D, b0 + (size_t)l * D,
            W1 + (size_t)l * D * D, b1 + (size_t)l * D,
            gPrev, bPrev, V, invV);

        agg_kernel<<<592, 256>>>(statsP + l * 2 * D, V);
    }

    norm_final<<<592, 256>>>(statsP + 2 * 2 * D,
                             gamma + 2 * (size_t)D, beta + 2 * (size_t)D,
                             features, out, V, invV);
}